// round 10
// baseline (speedup 1.0000x reference)
#include <cuda_runtime.h>
#include <cuda_bf16.h>

// Problem constants
#define BB 2
#define LL 2048
#define DD 1024
#define HH 16
#define HD 64

// Scratch (device globals — no allocation allowed)
__device__ float g_Q[BB*HH*LL*HD];    // (B,H,L,HD)
__device__ float g_K[BB*HH*LL*HD];
__device__ float g_V[BB*HH*LL*HD];
__device__ float g_CTX[BB*LL*DD];     // concat layout (B,L,H*HD)

// ---------------------------------------------------------------------------
// Kernel 1: fused QKV projection.
// grid = (BL/64, H, 3), block = 128. Tile 64x64, BK=16, 8x4 microtile/thread.
// q[b,h,l,e] = sum_d x[b,l,d] * W[h,d,e] + bias[h,e]
// ---------------------------------------------------------------------------
__global__ __launch_bounds__(128) void qkv_kernel(
    const float* __restrict__ x,
    const float* __restrict__ Wq, const float* __restrict__ bq,
    const float* __restrict__ Wk, const float* __restrict__ bk,
    const float* __restrict__ Wv, const float* __restrict__ bv)
{
    const int h   = blockIdx.y;
    const int mat = blockIdx.z;

    const float* W;  const float* bias;  float* out;
    if (mat == 0)      { W = Wq + h*DD*HD; bias = bq + h*HD; out = g_Q; }
    else if (mat == 1) { W = Wk + h*DD*HD; bias = bk + h*HD; out = g_K; }
    else               { W = Wv + h*DD*HD; bias = bv + h*HD; out = g_V; }

    __shared__ float As[16][65];   // transposed A tile, padded
    __shared__ float Bs[16][64];

    const int tid = threadIdx.x;
    const int tx  = tid & 15;      // 16 col groups * 4 = 64
    const int ty  = tid >> 4;      // 8 row groups * 8 = 64
    const int row0 = blockIdx.x * 64;

    float acc[8][4];
    #pragma unroll
    for (int i = 0; i < 8; i++)
        #pragma unroll
        for (int j = 0; j < 4; j++) acc[i][j] = 0.f;

    for (int k0 = 0; k0 < DD; k0 += 16) {
        // A tile: 64 rows x 16 k (256 float4, 2 per thread), stored transposed
        #pragma unroll
        for (int i = 0; i < 2; i++) {
            int idx = tid + i*128;
            int r   = idx >> 2;
            int kc  = (idx & 3) * 4;
            float4 v = *(const float4*)&x[(row0 + r)*DD + k0 + kc];
            As[kc+0][r] = v.x; As[kc+1][r] = v.y; As[kc+2][r] = v.z; As[kc+3][r] = v.w;
        }
        // B tile: 16 k x 64 n
        #pragma unroll
        for (int i = 0; i < 2; i++) {
            int idx = tid + i*128;
            int kr  = idx >> 4;
            int nc  = (idx & 15) * 4;
            *(float4*)&Bs[kr][nc] = *(const float4*)&W[(k0 + kr)*HD + nc];
        }
        __syncthreads();
        #pragma unroll
        for (int kk = 0; kk < 16; kk++) {
            float a[8], bb[4];
            #pragma unroll
            for (int i = 0; i < 8; i++) a[i] = As[kk][ty*8 + i];
            #pragma unroll
            for (int j = 0; j < 4; j++) bb[j] = Bs[kk][tx*4 + j];
            #pragma unroll
            for (int i = 0; i < 8; i++)
                #pragma unroll
                for (int j = 0; j < 4; j++)
                    acc[i][j] += a[i] * bb[j];
        }
        __syncthreads();
    }

    // Write to (B,H,L,HD) layout
    #pragma unroll
    for (int i = 0; i < 8; i++) {
        int r = row0 + ty*8 + i;
        int b = r >> 11;           // L = 2048
        int l = r & 2047;
        float* orow = out + ((size_t)(b*HH + h)*LL + l)*HD;
        #pragma unroll
        for (int j = 0; j < 4; j++) {
            int n = tx*4 + j;
            orow[n] = acc[i][j] + bias[n];
        }
    }
}

// ---------------------------------------------------------------------------
// Kernel 2: flash attention, 1 thread = 1 query row.
// grid = (L/128, B*H), block = 128. K/V staged as 64-key tiles in smem.
// Online softmax with lazy rescale. Writes ctx directly in concat layout.
// ---------------------------------------------------------------------------
__global__ __launch_bounds__(128) void attn_kernel(const int* __restrict__ mask)
{
    const int bh = blockIdx.y;
    const int b  = bh >> 4;             // H = 16
    const int q  = blockIdx.x * 128 + threadIdx.x;
    const int h  = bh & 15;

    const float4* Qrow  = (const float4*)(g_Q + (((size_t)bh)*LL + q)*HD);
    const float4* Kbase = (const float4*)(g_K + ((size_t)bh)*LL*HD);
    const float4* Vbase = (const float4*)(g_V + ((size_t)bh)*LL*HD);

    __shared__ float4 Ks[64*16];        // 64 keys x 64 floats
    __shared__ float4 Vs[64*16];
    __shared__ int    ms[64];

    float4 qv[16];
    #pragma unroll
    for (int i = 0; i < 16; i++) qv[i] = Qrow[i];

    float o[64];
    #pragma unroll
    for (int e = 0; e < 64; e++) o[e] = 0.f;
    float m = -1e30f, l = 0.f;

    for (int kt = 0; kt < LL/64; kt++) {
        __syncthreads();
        #pragma unroll
        for (int i = 0; i < 8; i++) {
            int idx = threadIdx.x + i*128;          // 1024 float4 per tile
            Ks[idx] = Kbase[kt*64*16 + idx];
            Vs[idx] = Vbase[kt*64*16 + idx];
        }
        if (threadIdx.x < 64) ms[threadIdx.x] = mask[b*LL + kt*64 + threadIdx.x];
        __syncthreads();

        for (int j = 0; j < 64; j++) {
            const float4* kr = &Ks[j*16];
            float s = 0.f;
            #pragma unroll
            for (int e = 0; e < 16; e++) {
                float4 kk = kr[e];
                s += qv[e].x*kk.x + qv[e].y*kk.y + qv[e].z*kk.z + qv[e].w*kk.w;
            }
            s *= 0.125f;                           // 1/sqrt(64)
            if (ms[j] == 0) s = -1e9f;

            if (s > m) {                           // lazy rescale (rare after warmup)
                float corr = __expf(m - s);
                l *= corr;
                #pragma unroll
                for (int e = 0; e < 64; e++) o[e] *= corr;
                m = s;
            }
            float p = __expf(s - m);
            l += p;
            const float4* vr = &Vs[j*16];
            #pragma unroll
            for (int e = 0; e < 16; e++) {
                float4 vv = vr[e];
                o[4*e+0] += p*vv.x; o[4*e+1] += p*vv.y;
                o[4*e+2] += p*vv.z; o[4*e+3] += p*vv.w;
            }
        }
    }

    const float inv = 1.0f / l;
    float* crow = g_CTX + ((size_t)(b*LL + q))*DD + h*HD;
    #pragma unroll
    for (int e = 0; e < 64; e++) crow[e] = o[e] * inv;
}

// ---------------------------------------------------------------------------
// Kernel 3: output projection. out = ctx @ Wo + bo.
// M=4096, N=1024, K=1024. Same 64x64/BK16 tiling as kernel 1.
// ---------------------------------------------------------------------------
__global__ __launch_bounds__(128) void out_proj_kernel(
    const float* __restrict__ Wo, const float* __restrict__ bo,
    float* __restrict__ out)
{
    __shared__ float As[16][65];
    __shared__ float Bs[16][64];

    const int tid = threadIdx.x;
    const int tx  = tid & 15;
    const int ty  = tid >> 4;
    const int row0 = blockIdx.x * 64;
    const int n0   = blockIdx.y * 64;

    float acc[8][4];
    #pragma unroll
    for (int i = 0; i < 8; i++)
        #pragma unroll
        for (int j = 0; j < 4; j++) acc[i][j] = 0.f;

    for (int k0 = 0; k0 < DD; k0 += 16) {
        #pragma unroll
        for (int i = 0; i < 2; i++) {
            int idx = tid + i*128;
            int r   = idx >> 2;
            int kc  = (idx & 3) * 4;
            float4 v = *(const float4*)&g_CTX[(size_t)(row0 + r)*DD + k0 + kc];
            As[kc+0][r] = v.x; As[kc+1][r] = v.y; As[kc+2][r] = v.z; As[kc+3][r] = v.w;
        }
        #pragma unroll
        for (int i = 0; i < 2; i++) {
            int idx = tid + i*128;
            int kr  = idx >> 4;
            int nc  = (idx & 15) * 4;
            *(float4*)&Bs[kr][nc] = *(const float4*)&Wo[(size_t)(k0 + kr)*DD + n0 + nc];
        }
        __syncthreads();
        #pragma unroll
        for (int kk = 0; kk < 16; kk++) {
            float a[8], bb[4];
            #pragma unroll
            for (int i = 0; i < 8; i++) a[i] = As[kk][ty*8 + i];
            #pragma unroll
            for (int j = 0; j < 4; j++) bb[j] = Bs[kk][tx*4 + j];
            #pragma unroll
            for (int i = 0; i < 8; i++)
                #pragma unroll
                for (int j = 0; j < 4; j++)
                    acc[i][j] += a[i] * bb[j];
        }
        __syncthreads();
    }

    #pragma unroll
    for (int i = 0; i < 8; i++) {
        int r = row0 + ty*8 + i;
        float* orow = out + (size_t)r*DD + n0;
        #pragma unroll
        for (int j = 0; j < 4; j++) {
            int n = tx*4 + j;
            orow[n] = acc[i][j] + bo[n0 + n];
        }
    }
}

// ---------------------------------------------------------------------------
extern "C" void kernel_launch(void* const* d_in, const int* in_sizes, int n_in,
                              void* d_out, int out_size)
{
    const float* x    = (const float*)d_in[0];
    const int*   mask = (const int*)  d_in[1];
    const float* Wq   = (const float*)d_in[2];
    const float* bq   = (const float*)d_in[3];
    const float* Wk   = (const float*)d_in[4];
    const float* bk   = (const float*)d_in[5];
    const float* Wv   = (const float*)d_in[6];
    const float* bv   = (const float*)d_in[7];
    const float* Wo   = (const float*)d_in[8];
    const float* bo   = (const float*)d_in[9];
    float* out = (float*)d_out;

    dim3 g1(BB*LL/64, HH, 3);            // (64, 16, 3)
    qkv_kernel<<<g1, 128>>>(x, Wq, bq, Wk, bk, Wv, bv);

    dim3 g2(LL/128, BB*HH);              // (16, 32)
    attn_kernel<<<g2, 128>>>(mask);

    dim3 g3(BB*LL/64, DD/64);            // (64, 16)
    out_proj_kernel<<<g3, 128>>>(Wo, bo, out);
}

// round 11
// speedup vs baseline: 1.2623x; 1.2623x over previous
#include <cuda_runtime.h>
#include <cuda_bf16.h>

// Problem constants
#define BB 2
#define LL 2048
#define DD 1024
#define HH 16
#define HD 64

// Scratch (device globals — no allocation allowed)
__device__ float g_Q[BB*HH*LL*HD];    // (B,H,L,HD)
__device__ float g_K[BB*HH*LL*HD];
__device__ float g_V[BB*HH*LL*HD];
__device__ float g_CTX[BB*LL*DD];     // concat layout (B,L,H*HD)

// ---------------------------------------------------------------------------
// Kernel 1: fused QKV projection.
// grid = (BL/64, H, 3), block = 128. Tile 64x64, BK=16, 8x4 microtile/thread.
// Vectorized smem reads: 3 LDS.128 per k-step instead of 12 scalar LDS.
// ---------------------------------------------------------------------------
__global__ __launch_bounds__(128) void qkv_kernel(
    const float* __restrict__ x,
    const float* __restrict__ Wq, const float* __restrict__ bq,
    const float* __restrict__ Wk, const float* __restrict__ bk,
    const float* __restrict__ Wv, const float* __restrict__ bv)
{
    const int h   = blockIdx.y;
    const int mat = blockIdx.z;

    const float* W;  const float* bias;  float* out;
    if (mat == 0)      { W = Wq + h*DD*HD; bias = bq + h*HD; out = g_Q; }
    else if (mat == 1) { W = Wk + h*DD*HD; bias = bk + h*HD; out = g_K; }
    else               { W = Wv + h*DD*HD; bias = bv + h*HD; out = g_V; }

    __shared__ float As[16][68];   // transposed A tile, float4-friendly pad
    __shared__ float Bs[16][68];

    const int tid = threadIdx.x;
    const int tx  = tid & 15;      // 16 col groups * 4 = 64
    const int ty  = tid >> 4;      // 8 row groups * 8 = 64
    const int row0 = blockIdx.x * 64;

    float acc[8][4];
    #pragma unroll
    for (int i = 0; i < 8; i++)
        #pragma unroll
        for (int j = 0; j < 4; j++) acc[i][j] = 0.f;

    for (int k0 = 0; k0 < DD; k0 += 16) {
        // A tile: 64 rows x 16 k, stored transposed
        #pragma unroll
        for (int i = 0; i < 2; i++) {
            int idx = tid + i*128;
            int r   = idx >> 2;
            int kc  = (idx & 3) * 4;
            float4 v = *(const float4*)&x[(row0 + r)*DD + k0 + kc];
            As[kc+0][r] = v.x; As[kc+1][r] = v.y; As[kc+2][r] = v.z; As[kc+3][r] = v.w;
        }
        // B tile: 16 k x 64 n
        #pragma unroll
        for (int i = 0; i < 2; i++) {
            int idx = tid + i*128;
            int kr  = idx >> 4;
            int nc  = (idx & 15) * 4;
            *(float4*)&Bs[kr][nc] = *(const float4*)&W[(k0 + kr)*HD + nc];
        }
        __syncthreads();
        #pragma unroll
        for (int kk = 0; kk < 16; kk++) {
            float4 a0 = *(const float4*)&As[kk][ty*8];
            float4 a1 = *(const float4*)&As[kk][ty*8 + 4];
            float4 bv4 = *(const float4*)&Bs[kk][tx*4];
            float a[8] = {a0.x,a0.y,a0.z,a0.w,a1.x,a1.y,a1.z,a1.w};
            #pragma unroll
            for (int i = 0; i < 8; i++) {
                acc[i][0] += a[i]*bv4.x;
                acc[i][1] += a[i]*bv4.y;
                acc[i][2] += a[i]*bv4.z;
                acc[i][3] += a[i]*bv4.w;
            }
        }
        __syncthreads();
    }

    #pragma unroll
    for (int i = 0; i < 8; i++) {
        int r = row0 + ty*8 + i;
        int b = r >> 11;           // L = 2048
        int l = r & 2047;
        float* orow = out + ((size_t)(b*HH + h)*LL + l)*HD;
        #pragma unroll
        for (int j = 0; j < 4; j++) {
            int n = tx*4 + j;
            orow[n] = acc[i][j] + bias[n];
        }
    }
}

// ---------------------------------------------------------------------------
// Kernel 2: flash attention, register-tiled two-GEMM formulation.
// grid = (L/64, B*H), block = 128 (8x4 microtile over a 64q x 64k tile).
// S = Q K^T as smem GEMM (K stored with XOR-float4 swizzle for conflict-free
// cross-row reads), online softmax with 16-lane shfl reductions, then
// C += P V as smem GEMM. P overwrites the K buffer -> 48 KB static smem total.
// ---------------------------------------------------------------------------
__global__ __launch_bounds__(128) void attn_kernel(const int* __restrict__ mask)
{
    __shared__ float Qs[64*64];
    __shared__ float KP[64*64];    // K (swizzled), reused as P (natural)
    __shared__ float Vs[64*64];

    const int bh = blockIdx.y;
    const int b  = bh >> 4;
    const int h  = bh & 15;
    const int q0 = blockIdx.x * 64;
    const int tid = threadIdx.x;
    const int tx = tid & 15;
    const int ty = tid >> 4;

    const float* Qb = g_Q + ((size_t)bh*LL + q0)*HD;
    const float* Kb = g_K + (size_t)bh*LL*HD;
    const float* Vb = g_V + (size_t)bh*LL*HD;
    const int*   mb = mask + b*LL;

    // Load Q tile (64 x 64)
    #pragma unroll
    for (int i = 0; i < 8; i++) {
        int idx = tid + i*128;
        int r = idx >> 4, e4 = idx & 15;
        *(float4*)&Qs[r*64 + e4*4] = *(const float4*)(Qb + r*64 + e4*4);
    }

    float c[8][4];
    float m_[8], l_[8];
    #pragma unroll
    for (int i = 0; i < 8; i++) {
        m_[i] = -1e30f; l_[i] = 0.f;
        #pragma unroll
        for (int j = 0; j < 4; j++) c[i][j] = 0.f;
    }

    for (int kt = 0; kt < LL/64; kt++) {
        const float* Kt = Kb + (size_t)kt*64*HD;
        const float* Vt = Vb + (size_t)kt*64*HD;

        __syncthreads();   // previous tile's PV reads / Q store done
        #pragma unroll
        for (int i = 0; i < 8; i++) {
            int idx = tid + i*128;
            int key = idx >> 4, e4 = idx & 15;
            float4 kv = *(const float4*)(Kt + key*64 + e4*4);
            // XOR swizzle at float4 granularity: slot (e4 ^ (key&15))
            *(float4*)&KP[key*64 + ((e4 ^ (key & 15)) << 2)] = kv;
            *(float4*)&Vs[key*64 + e4*4] = *(const float4*)(Vt + key*64 + e4*4);
        }
        __syncthreads();

        // ---- S = Q K^T : thread cols are keys {tx, tx+16, tx+32, tx+48} ----
        float s[8][4];
        #pragma unroll
        for (int i = 0; i < 8; i++)
            #pragma unroll
            for (int j = 0; j < 4; j++) s[i][j] = 0.f;

        #pragma unroll
        for (int e4 = 0; e4 < 16; e4++) {
            const int xe = ((e4 ^ tx) << 2);    // (key&15)==tx for all 4 cols
            float4 b0 = *(const float4*)&KP[(tx      )*64 + xe];
            float4 b1 = *(const float4*)&KP[(tx + 16)*64 + xe];
            float4 b2 = *(const float4*)&KP[(tx + 32)*64 + xe];
            float4 b3 = *(const float4*)&KP[(tx + 48)*64 + xe];
            #pragma unroll
            for (int i = 0; i < 8; i++) {
                float4 a = *(const float4*)&Qs[(ty*8 + i)*64 + e4*4];
                s[i][0] += a.x*b0.x + a.y*b0.y + a.z*b0.z + a.w*b0.w;
                s[i][1] += a.x*b1.x + a.y*b1.y + a.z*b1.z + a.w*b1.w;
                s[i][2] += a.x*b2.x + a.y*b2.y + a.z*b2.z + a.w*b2.w;
                s[i][3] += a.x*b3.x + a.y*b3.y + a.z*b3.z + a.w*b3.w;
            }
        }
        __syncthreads();   // all K reads complete before P overwrites KP

        int mk0 = mb[kt*64 + tx];
        int mk1 = mb[kt*64 + tx + 16];
        int mk2 = mb[kt*64 + tx + 32];
        int mk3 = mb[kt*64 + tx + 48];

        // ---- online softmax (rows spread over 16 tx lanes) ----
        #pragma unroll
        for (int i = 0; i < 8; i++) {
            float s0 = mk0 ? s[i][0]*0.125f : -1e9f;
            float s1 = mk1 ? s[i][1]*0.125f : -1e9f;
            float s2 = mk2 ? s[i][2]*0.125f : -1e9f;
            float s3 = mk3 ? s[i][3]*0.125f : -1e9f;
            float rm = fmaxf(fmaxf(s0, s1), fmaxf(s2, s3));
            rm = fmaxf(rm, __shfl_xor_sync(0xffffffffu, rm, 1));
            rm = fmaxf(rm, __shfl_xor_sync(0xffffffffu, rm, 2));
            rm = fmaxf(rm, __shfl_xor_sync(0xffffffffu, rm, 4));
            rm = fmaxf(rm, __shfl_xor_sync(0xffffffffu, rm, 8));
            float mnew = fmaxf(m_[i], rm);
            float corr = __expf(m_[i] - mnew);
            float p0 = __expf(s0 - mnew);
            float p1 = __expf(s1 - mnew);
            float p2 = __expf(s2 - mnew);
            float p3 = __expf(s3 - mnew);
            float rs = (p0 + p1) + (p2 + p3);
            rs += __shfl_xor_sync(0xffffffffu, rs, 1);
            rs += __shfl_xor_sync(0xffffffffu, rs, 2);
            rs += __shfl_xor_sync(0xffffffffu, rs, 4);
            rs += __shfl_xor_sync(0xffffffffu, rs, 8);
            m_[i] = mnew;
            l_[i] = l_[i]*corr + rs;
            c[i][0] *= corr; c[i][1] *= corr; c[i][2] *= corr; c[i][3] *= corr;
            int ro = (ty*8 + i)*64;
            KP[ro + tx     ] = p0;
            KP[ro + tx + 16] = p1;
            KP[ro + tx + 32] = p2;
            KP[ro + tx + 48] = p3;
        }
        __syncthreads();   // P visible

        // ---- C += P V : thread cols are HD dims tx*4 .. tx*4+3 ----
        #pragma unroll
        for (int k4 = 0; k4 < 16; k4++) {
            float4 v0 = *(const float4*)&Vs[(k4*4 + 0)*64 + tx*4];
            float4 v1 = *(const float4*)&Vs[(k4*4 + 1)*64 + tx*4];
            float4 v2 = *(const float4*)&Vs[(k4*4 + 2)*64 + tx*4];
            float4 v3 = *(const float4*)&Vs[(k4*4 + 3)*64 + tx*4];
            #pragma unroll
            for (int i = 0; i < 8; i++) {
                float4 p = *(const float4*)&KP[(ty*8 + i)*64 + k4*4];
                c[i][0] += p.x*v0.x + p.y*v1.x + p.z*v2.x + p.w*v3.x;
                c[i][1] += p.x*v0.y + p.y*v1.y + p.z*v2.y + p.w*v3.y;
                c[i][2] += p.x*v0.z + p.y*v1.z + p.z*v2.z + p.w*v3.z;
                c[i][3] += p.x*v0.w + p.y*v1.w + p.z*v2.w + p.w*v3.w;
            }
        }
    }

    // Epilogue: normalize and write concat layout
    #pragma unroll
    for (int i = 0; i < 8; i++) {
        float inv = 1.0f / l_[i];
        int q = q0 + ty*8 + i;
        float* orow = g_CTX + ((size_t)b*LL + q)*DD + h*HD;
        *(float4*)(orow + tx*4) =
            make_float4(c[i][0]*inv, c[i][1]*inv, c[i][2]*inv, c[i][3]*inv);
    }
}

// ---------------------------------------------------------------------------
// Kernel 3: output projection. out = ctx @ Wo + bo.
// M=4096, N=1024, K=1024. Vectorized inner loop like kernel 1.
// ---------------------------------------------------------------------------
__global__ __launch_bounds__(128) void out_proj_kernel(
    const float* __restrict__ Wo, const float* __restrict__ bo,
    float* __restrict__ out)
{
    __shared__ float As[16][68];
    __shared__ float Bs[16][68];

    const int tid = threadIdx.x;
    const int tx  = tid & 15;
    const int ty  = tid >> 4;
    const int row0 = blockIdx.x * 64;
    const int n0   = blockIdx.y * 64;

    float acc[8][4];
    #pragma unroll
    for (int i = 0; i < 8; i++)
        #pragma unroll
        for (int j = 0; j < 4; j++) acc[i][j] = 0.f;

    for (int k0 = 0; k0 < DD; k0 += 16) {
        #pragma unroll
        for (int i = 0; i < 2; i++) {
            int idx = tid + i*128;
            int r   = idx >> 2;
            int kc  = (idx & 3) * 4;
            float4 v = *(const float4*)&g_CTX[(size_t)(row0 + r)*DD + k0 + kc];
            As[kc+0][r] = v.x; As[kc+1][r] = v.y; As[kc+2][r] = v.z; As[kc+3][r] = v.w;
        }
        #pragma unroll
        for (int i = 0; i < 2; i++) {
            int idx = tid + i*128;
            int kr  = idx >> 4;
            int nc  = (idx & 15) * 4;
            *(float4*)&Bs[kr][nc] = *(const float4*)&Wo[(size_t)(k0 + kr)*DD + n0 + nc];
        }
        __syncthreads();
        #pragma unroll
        for (int kk = 0; kk < 16; kk++) {
            float4 a0 = *(const float4*)&As[kk][ty*8];
            float4 a1 = *(const float4*)&As[kk][ty*8 + 4];
            float4 bv4 = *(const float4*)&Bs[kk][tx*4];
            float a[8] = {a0.x,a0.y,a0.z,a0.w,a1.x,a1.y,a1.z,a1.w};
            #pragma unroll
            for (int i = 0; i < 8; i++) {
                acc[i][0] += a[i]*bv4.x;
                acc[i][1] += a[i]*bv4.y;
                acc[i][2] += a[i]*bv4.z;
                acc[i][3] += a[i]*bv4.w;
            }
        }
        __syncthreads();
    }

    #pragma unroll
    for (int i = 0; i < 8; i++) {
        int r = row0 + ty*8 + i;
        float* orow = out + (size_t)r*DD + n0;
        #pragma unroll
        for (int j = 0; j < 4; j++) {
            int n = tx*4 + j;
            orow[n] = acc[i][j] + bo[n0 + n];
        }
    }
}

// ---------------------------------------------------------------------------
extern "C" void kernel_launch(void* const* d_in, const int* in_sizes, int n_in,
                              void* d_out, int out_size)
{
    const float* x    = (const float*)d_in[0];
    const int*   mask = (const int*)  d_in[1];
    const float* Wq   = (const float*)d_in[2];
    const float* bq   = (const float*)d_in[3];
    const float* Wk   = (const float*)d_in[4];
    const float* bk   = (const float*)d_in[5];
    const float* Wv   = (const float*)d_in[6];
    const float* bv   = (const float*)d_in[7];
    const float* Wo   = (const float*)d_in[8];
    const float* bo   = (const float*)d_in[9];
    float* out = (float*)d_out;

    dim3 g1(BB*LL/64, HH, 3);            // (64, 16, 3)
    qkv_kernel<<<g1, 128>>>(x, Wq, bq, Wk, bk, Wv, bv);

    dim3 g2(LL/64, BB*HH);               // (32, 32)
    attn_kernel<<<g2, 128>>>(mask);

    dim3 g3(BB*LL/64, DD/64);            // (64, 16)
    out_proj_kernel<<<g3, 128>>>(Wo, bo, out);
}